// round 13
// baseline (speedup 1.0000x reference)
#include <cuda_runtime.h>
#include <math.h>

#define BATCH 512
#define LEN   256
#define DIM   64
#define HIDN  256
#define TOPK  128
#define NBINS 2048
#define CAND  1024
#define BCAP  256

typedef unsigned long long ull;

__device__ __forceinline__ ull pk2(float lo, float hi) {
    ull r;
    asm("mov.b64 %0, {%1, %2};" : "=l"(r) : "f"(lo), "f"(hi));
    return r;
}
__device__ __forceinline__ void upk2(ull v, float& lo, float& hi) {
    asm("mov.b64 {%0, %1}, %2;" : "=f"(lo), "=f"(hi) : "l"(v));
}
__device__ __forceinline__ void fma2(ull& d, ull a, ull b) {
    asm("fma.rn.f32x2 %0, %1, %2, %0;" : "+l"(d) : "l"(a), "l"(b));
}

// ---------------- static scratch ----------------
__device__ float g_M[DIM * DIM];
__device__ float g_u[DIM];
__device__ float g_v[DIM];
__device__ float g_cc;
__device__ int   g_rows[BATCH * TOPK];
__device__ int   g_cols[BATCH * TOPK];
__device__ float g_wt[BATCH * TOPK];
__device__ float g_pooled[BATCH * HIDN];

// ---------------- kernel A: M = Wq Wk^T, u = Wq bk, v = Wk bq, cc = bq.bk ----
__global__ void kPrep(const float* __restrict__ Wq, const float* __restrict__ Wk,
                      const float* __restrict__ bq, const float* __restrict__ bk) {
    int tid = threadIdx.x;
    if (blockIdx.x < 16) {
        int idx = blockIdx.x * 256 + tid;
        int d  = idx >> 6;
        int dp = idx & 63;
        float acc = 0.f;
        #pragma unroll 8
        for (int h = 0; h < HIDN; h++) acc += Wq[d * HIDN + h] * Wk[dp * HIDN + h];
        g_M[idx] = acc;
    } else {
        if (tid < 64) {
            float a = 0.f;
            for (int h = 0; h < HIDN; h++) a += Wq[tid * HIDN + h] * bk[h];
            g_u[tid] = a;
        } else if (tid < 128) {
            int d = tid - 64;
            float a = 0.f;
            for (int h = 0; h < HIDN; h++) a += Wk[d * HIDN + h] * bq[h];
            g_v[d] = a;
        } else if (tid == 128) {
            float a = 0.f;
            for (int h = 0; h < HIDN; h++) a += bq[h] * bk[h];
            g_cc = a;
        }
    }
}

// ---------------- fused: scores + exact top-128 set (sort-free) + softmax ----
// smem floats: sX 16640 + sGw 4096 + sA 256 + sC 256 + hist 2048 + coarse 128
//   + cvals 1024 + cidx 1024 + wred 16 + fvals 128 + fidx 128 + bvals 256 + bidx 256
#define ST_SMEM_FLOATS (16640 + 4096 + 256 + 256 + 2048 + 128 + 1024 + 1024 + 16 + 128 + 128 + 256 + 256)
__global__ __launch_bounds__(256, 2) void kScoresTopK(const float* __restrict__ x) {
    extern __shared__ float sm[];
    float* sX   = sm;                 // [64 d][260]
    float* sGw  = sX + 16640;         // per-warp: [8w][64 d][8 r]
    float* sA   = sGw + 4096;         // 256
    float* sC   = sA + 256;           // 256
    unsigned int* hist   = (unsigned int*)(sC + 256);    // 2048
    unsigned int* coarse = hist + NBINS;                  // 128
    float* cvals = (float*)(coarse + 128);                // 1024
    int*   cidx  = (int*)(cvals + CAND);                  // 1024
    float* wred  = (float*)(cidx + CAND);                 // 16
    float* fvals = wred + 16;                             // 128
    int*   fidx  = (int*)(fvals + 128);                   // 128
    float* bvals = (float*)(fidx + 128);                  // 256
    int*   bidx  = (int*)(bvals + BCAP);                  // 256
    __shared__ unsigned int s_cnt, s_nfin, s_nbnd;
    __shared__ int s_tb;
    __shared__ float s_minv, s_binw, s_gmax, s_fmin;
    __shared__ float sred[128];

    int b = blockIdx.x, tid = threadIdx.x;
    int lane = tid & 31, wid = tid >> 5;   // wid 0..7
    const float* xb = x + (size_t)b * LEN * DIM;
    float* sGwW = sGw + wid * 512;         // this warp's [64 d][8 r] tile

    // load x^T: sX[d][m] = x[m][d]
    for (int t = tid; t < LEN * DIM; t += 256) {
        int m = t >> 6, d = t & 63;
        sX[d * 260 + m] = xb[m * DIM + d];
    }
    if (tid == 0) { s_cnt = 0u; s_gmax = -3.4e38f; s_fmin = 3.4e38f; }
    __syncthreads();

    // bias rows
    {
        int l = tid;
        float a = 0.f, c = 0.f;
        #pragma unroll 8
        for (int d = 0; d < DIM; d++) {
            float xv = sX[d * 260 + l];
            a += xv * g_u[d];
            c += xv * g_v[d];
        }
        sA[l] = a; sC[l] = c;
    }
    float ccv = g_cc;
    __syncthreads();

    const float scale = 0.0625f;   // 256^-0.5
    int mA = lane * 4;             // cols mA..+3 and mA+128..+131

    for (int chunk = 0; chunk < 4; chunk++) {
        int l0 = chunk * 64 + wid * 8;

        // ---- per-warp G tile: Gw[d][r] = sum_dd x[l0+r][dd] * M[dd][d] ----
        {
            float acc2[8][2];
            #pragma unroll
            for (int r = 0; r < 8; r++) { acc2[r][0] = 0.f; acc2[r][1] = 0.f; }
            #pragma unroll 4
            for (int dd = 0; dd < DIM; dd++) {
                float4 xq0 = *(const float4*)(sX + dd * 260 + l0);      // broadcast
                float4 xq1 = *(const float4*)(sX + dd * 260 + l0 + 4);
                float m0 = g_M[dd * 64 + lane];
                float m1 = g_M[dd * 64 + lane + 32];
                float xv[8] = {xq0.x, xq0.y, xq0.z, xq0.w, xq1.x, xq1.y, xq1.z, xq1.w};
                #pragma unroll
                for (int r = 0; r < 8; r++) {
                    acc2[r][0] += xv[r] * m0;
                    acc2[r][1] += xv[r] * m1;
                }
            }
            #pragma unroll
            for (int r = 0; r < 8; r++) {
                sGwW[lane * 8 + r]        = acc2[r][0];
                sGwW[(lane + 32) * 8 + r] = acc2[r][1];
            }
            __syncwarp();
        }

        // ---- GEMM 8x8 tile, f32x2 packed ----
        ull accp[8][4];
        #pragma unroll
        for (int r = 0; r < 8; r++)
            #pragma unroll
            for (int c = 0; c < 4; c++) accp[r][c] = 0ull;

        #pragma unroll 4
        for (int d = 0; d < DIM; d++) {
            float4 g0 = *(const float4*)(sGwW + d * 8);       // broadcast
            float4 g1 = *(const float4*)(sGwW + d * 8 + 4);
            float4 xa = *(const float4*)(sX + d * 260 + mA);
            float4 xc = *(const float4*)(sX + d * 260 + mA + 128);
            ull xp0 = pk2(xa.x, xa.y), xp1 = pk2(xa.z, xa.w);
            ull xp2 = pk2(xc.x, xc.y), xp3 = pk2(xc.z, xc.w);
            float gv[8] = {g0.x, g0.y, g0.z, g0.w, g1.x, g1.y, g1.z, g1.w};
            #pragma unroll
            for (int r = 0; r < 8; r++) {
                ull rr = pk2(gv[r], gv[r]);
                fma2(accp[r][0], rr, xp0);
                fma2(accp[r][1], rr, xp1);
                fma2(accp[r][2], rr, xp2);
                fma2(accp[r][3], rr, xp3);
            }
        }

        // epilogue: bias + scale, repack, min/max
        float lmin = 3.4e38f, lmax = -3.4e38f;
        #pragma unroll
        for (int r = 0; r < 8; r++) {
            float base = sA[l0 + r] + ccv;
            #pragma unroll
            for (int cp = 0; cp < 4; cp++) {
                float lo, hi;
                upk2(accp[r][cp], lo, hi);
                int c0 = cp * 2;
                int m0 = (c0 < 4) ? (mA + c0) : (mA + 124 + c0);
                float v0 = scale * (lo + base + sC[m0]);
                float v1 = scale * (hi + base + sC[m0 + 1]);
                accp[r][cp] = pk2(v0, v1);
                lmin = fminf(lmin, fminf(v0, v1));
                lmax = fmaxf(lmax, fmaxf(v0, v1));
            }
        }
        #pragma unroll
        for (int o = 16; o > 0; o >>= 1) {
            lmin = fminf(lmin, __shfl_xor_sync(0xffffffffu, lmin, o));
            lmax = fmaxf(lmax, __shfl_xor_sync(0xffffffffu, lmax, o));
        }
        if (lane == 0) { wred[wid] = lmin; wred[8 + wid] = lmax; }
        for (int t = tid; t < NBINS; t += 256) hist[t] = 0u;
        __syncthreads();                                        // (1)
        if (tid == 0) {
            float mn = wred[0], mx = wred[8];
            #pragma unroll
            for (int w = 1; w < 8; w++) {
                mn = fminf(mn, wred[w]);
                mx = fmaxf(mx, wred[8 + w]);
            }
            s_minv = mn;
            s_binw = fmaxf(mx - mn, 1e-20f) / (float)NBINS;
            s_gmax = fmaxf(s_gmax, mx);
        }
        __syncthreads();                                        // (2)
        float minv = s_minv;
        float invw = 1.0f / s_binw;

        // histogram from packed registers
        #pragma unroll
        for (int r = 0; r < 8; r++)
            #pragma unroll
            for (int cp = 0; cp < 4; cp++) {
                float lo, hi;
                upk2(accp[r][cp], lo, hi);
                int b0 = (int)((lo - minv) * invw);
                int b1 = (int)((hi - minv) * invw);
                b0 = min(max(b0, 0), NBINS - 1);
                b1 = min(max(b1, 0), NBINS - 1);
                atomicAdd(&hist[b0], 1u);
                atomicAdd(&hist[b1], 1u);
            }
        __syncthreads();                                        // (3)
        if (tid < 128) {
            unsigned int s = 0;
            #pragma unroll
            for (int k = 0; k < 16; k++) s += hist[tid * 16 + k];
            coarse[tid] = s;
        }
        __syncthreads();                                        // (4)
        // warp0 suffix scan over 128 coarse groups -> exact threshold bin s_tb
        if (wid == 0) {
            unsigned int g0c = coarse[lane * 4], g1c = coarse[lane * 4 + 1];
            unsigned int g2c = coarse[lane * 4 + 2], g3c = coarse[lane * 4 + 3];
            unsigned int sfx = g0c + g1c + g2c + g3c;
            #pragma unroll
            for (int off = 1; off < 32; off <<= 1) {
                unsigned int v = __shfl_down_sync(0xffffffffu, sfx, off);
                if (lane + off < 32) sfx += v;
            }
            unsigned int sfx_next = __shfl_down_sync(0xffffffffu, sfx, 1);
            if (lane == 31) sfx_next = 0u;
            unsigned int ball = __ballot_sync(0xffffffffu, sfx >= TOPK);
            int lc = 31 - __clz(ball);
            if (lane == lc) {
                unsigned int gs[4] = {g0c, g1c, g2c, g3c};
                unsigned int cum = sfx_next;
                int found = 0;
                for (int gi = 3; gi >= 0; gi--) {
                    if (cum + gs[gi] >= TOPK) { found = gi; break; }
                    cum += gs[gi];
                }
                int gbase = (lc * 4 + found) * 16;
                unsigned int cc = cum;
                int tbin = gbase;
                for (int f = gbase + 15; f >= gbase; f--) {
                    cc += hist[f];
                    if (cc >= TOPK) { tbin = f; break; }
                }
                s_tb = tbin;
            }
        }
        __syncthreads();                                        // (5)
        int tb = s_tb;
        if (tid == 0) s_fmin = fminf(s_fmin, minv + (float)tb * s_binw - s_binw);

        // collect candidates: bin >= tb (bin-exact, no margin)
        #pragma unroll
        for (int r = 0; r < 8; r++)
            #pragma unroll
            for (int cp = 0; cp < 4; cp++) {
                float lo, hi;
                upk2(accp[r][cp], lo, hi);
                int c0 = cp * 2;
                int m0 = (c0 < 4) ? (mA + c0) : (mA + 124 + c0);
                int b0 = min(max((int)((lo - minv) * invw), 0), NBINS - 1);
                int b1 = min(max((int)((hi - minv) * invw), 0), NBINS - 1);
                if (b0 >= tb) {
                    unsigned int p = atomicAdd(&s_cnt, 1u);
                    if (p < CAND) { cvals[p] = lo; cidx[p] = (l0 + r) * LEN + m0; }
                }
                if (b1 >= tb) {
                    unsigned int p = atomicAdd(&s_cnt, 1u);
                    if (p < CAND) { cvals[p] = hi; cidx[p] = (l0 + r) * LEN + m0 + 1; }
                }
            }
        __syncthreads();                                        // (6)
    }

    // ---- final exact top-128 selection over candidates (sort-free) ----
    int C = (int)min(s_cnt, (unsigned int)CAND);
    for (int t = tid; t < NBINS; t += 256) hist[t] = 0u;
    if (tid == 0) {
        s_minv = s_fmin;
        s_binw = fmaxf(s_gmax - s_fmin, 1e-20f) / (float)NBINS;
        s_nfin = 0u; s_nbnd = 0u;
    }
    __syncthreads();
    float fminv = s_minv;
    float finvw = 1.0f / s_binw;
    for (int t = tid; t < C; t += 256) {
        int bn = min(max((int)((cvals[t] - fminv) * finvw), 0), NBINS - 1);
        atomicAdd(&hist[bn], 1u);
    }
    __syncthreads();
    if (tid < 128) {
        unsigned int s = 0;
        #pragma unroll
        for (int k = 0; k < 16; k++) s += hist[tid * 16 + k];
        coarse[tid] = s;
    }
    __syncthreads();
    if (wid == 0) {
        unsigned int g0c = coarse[lane * 4], g1c = coarse[lane * 4 + 1];
        unsigned int g2c = coarse[lane * 4 + 2], g3c = coarse[lane * 4 + 3];
        unsigned int sfx = g0c + g1c + g2c + g3c;
        #pragma unroll
        for (int off = 1; off < 32; off <<= 1) {
            unsigned int v = __shfl_down_sync(0xffffffffu, sfx, off);
            if (lane + off < 32) sfx += v;
        }
        unsigned int sfx_next = __shfl_down_sync(0xffffffffu, sfx, 1);
        if (lane == 31) sfx_next = 0u;
        unsigned int ball = __ballot_sync(0xffffffffu, sfx >= TOPK);
        int lc = 31 - __clz(ball);
        if (lane == lc) {
            unsigned int gs[4] = {g0c, g1c, g2c, g3c};
            unsigned int cum = sfx_next;
            int found = 0;
            for (int gi = 3; gi >= 0; gi--) {
                if (cum + gs[gi] >= TOPK) { found = gi; break; }
                cum += gs[gi];
            }
            int gbase = (lc * 4 + found) * 16;
            unsigned int cc = cum;
            int tbin = gbase;
            for (int f = gbase + 15; f >= gbase; f--) {
                cc += hist[f];
                if (cc >= TOPK) { tbin = f; break; }
            }
            s_tb = tbin;
        }
    }
    __syncthreads();
    int tb = s_tb;
    // split candidates: strictly-above bins -> final; boundary bin -> bvals
    for (int t = tid; t < C; t += 256) {
        float v = cvals[t];
        int bn = min(max((int)((v - fminv) * finvw), 0), NBINS - 1);
        if (bn > tb) {
            unsigned int p = atomicAdd(&s_nfin, 1u);
            fvals[p] = v; fidx[p] = cidx[t];
        } else if (bn == tb) {
            unsigned int p = atomicAdd(&s_nbnd, 1u);
            if (p < BCAP) { bvals[p] = v; bidx[p] = cidx[t]; }
        }
    }
    __syncthreads();
    // boundary: pick largest `need` via iterative warp argmax
    if (wid == 0) {
        int nfin = (int)s_nfin;
        int nb = min((int)s_nbnd, BCAP);
        int need = TOPK - nfin;
        for (int it = 0; it < need; it++) {
            float bestv = -3.4e38f; int bests = -1;
            for (int t = lane; t < nb; t += 32) {
                float v = bvals[t];
                if (v > bestv) { bestv = v; bests = t; }
            }
            #pragma unroll
            for (int off = 16; off > 0; off >>= 1) {
                float ov = __shfl_down_sync(0xffffffffu, bestv, off);
                int os = __shfl_down_sync(0xffffffffu, bests, off);
                if (ov > bestv) { bestv = ov; bests = os; }
            }
            bests = __shfl_sync(0xffffffffu, bests, 0);
            if (bests < 0) break;
            if (lane == 0) {
                fvals[nfin + it] = bvals[bests];
                fidx[nfin + it]  = bidx[bests];
                bvals[bests] = -3.4e38f;
            }
            __syncwarp();
        }
    }
    __syncthreads();

    // softmax over the 128-element set (order-free)
    float gmax = s_gmax;
    float e = 0.f;
    if (tid < TOPK) { e = expf(fvals[tid] - gmax); sred[tid] = e; }
    __syncthreads();
    for (int s = 64; s > 0; s >>= 1) {
        if (tid < s) sred[tid] += sred[tid + s];
        __syncthreads();
    }
    float denom = sred[0];
    if (tid < TOPK) {
        int idx = fidx[tid];
        g_rows[b * TOPK + tid] = idx >> 8;
        g_cols[b * TOPK + tid] = idx & 255;
        g_wt[b * TOPK + tid]   = e / denom;
    }
}

// ---------------- kernel E: pair features, W1 d-tiled (2 CTAs/SM) ----------
#define PR_SMEM_FLOATS (8192 + 16384 + 2048 + 256 + 256 + 128 + 128 + 128 + 128 + 128)
#define DT 32
__global__ __launch_bounds__(256, 2) void kPairs(const float* __restrict__ x,
                       const float* __restrict__ xi_w1, const float* __restrict__ xi_b1,
                       const float* __restrict__ xi_w2, const float* __restrict__ xi_b2,
                       const float* __restrict__ phi_w1, const float* __restrict__ phi_b1,
                       const float* __restrict__ phi_w2, const float* __restrict__ phi_b2) {
    extern __shared__ float sm[];
    float* sW1t  = sm;                    // [32 d][256 j] tile
    float* sXpT  = sW1t + 8192;           // [128 d][128 i]
    float* hpart = sXpT + 16384;          // [8][256]
    float* hxs   = hpart + 2048;          // 256
    float* hps   = hxs + 256;             // 256
    float* sw    = hps + 256;             // 128
    float* swxi  = sw + 128;              // 128
    int* srow  = (int*)(swxi + 128);      // 128
    int* scol  = srow + 128;              // 128
    int* dlist = scol + 128;              // 128
    __shared__ int   s_nd;
    __shared__ float s_swxi, s_swphi;

    int b = blockIdx.x, tid = threadIdx.x;
    int lane = tid & 31, wid = tid >> 5;  // wid 0..7

    if (tid < TOPK) {
        srow[tid] = g_rows[b * TOPK + tid];
        scol[tid] = g_cols[b * TOPK + tid];
        sw[tid]   = g_wt[b * TOPK + tid];
    }
    __syncthreads();

    // transposed pair matrix: rows 0..63 = x_row dims, 64..127 = x_col dims
    {
        int i = tid >> 1, half = tid & 1;
        int src = half ? scol[i] : srow[i];
        const float* xr = x + ((size_t)b * LEN + src) * DIM;
        #pragma unroll
        for (int dv = 0; dv < 16; dv++) {
            float4 v = *(const float4*)(xr + dv * 4);
            int d = half * 64 + dv * 4;
            sXpT[(d + 0) * 128 + i] = v.x;
            sXpT[(d + 1) * 128 + i] = v.y;
            sXpT[(d + 2) * 128 + i] = v.z;
            sXpT[(d + 3) * 128 + i] = v.w;
        }
    }
    if (tid == 0) {
        int nd = 0; float sphi = 0.f, sxi = 0.f;
        for (int i = 0; i < TOPK; i++) {
            if (srow[i] == scol[i]) { dlist[nd++] = i; sphi += sw[i]; }
            else sxi += sw[i];
        }
        s_nd = nd; s_swphi = sphi; s_swxi = sxi;
    }
    if (tid < TOPK) swxi[tid] = (srow[tid] == scol[tid]) ? 0.f : sw[tid];
    __syncthreads();

    // xi layer-1: f32x2 packed 8x8 tile, W1 streamed in 32-row d-tiles
    int jA = lane * 4;
    float4 b1a = *(const float4*)(xi_b1 + jA);
    float4 b1c = *(const float4*)(xi_b1 + jA + 128);
    ull bp0 = pk2(b1a.x, b1a.y), bp1 = pk2(b1a.z, b1a.w);
    ull bp2 = pk2(b1c.x, b1c.y), bp3 = pk2(b1c.z, b1c.w);
    float hbar[8] = {0.f, 0.f, 0.f, 0.f, 0.f, 0.f, 0.f, 0.f};

    for (int iter = 0; iter < 2; iter++) {
        int i0 = wid * 8 + iter * 64;  // warp-uniform i tile
        ull accp[8][4];
        #pragma unroll
        for (int r = 0; r < 8; r++) {
            accp[r][0] = bp0; accp[r][1] = bp1; accp[r][2] = bp2; accp[r][3] = bp3;
        }
        for (int dt = 0; dt < 128 / DT; dt++) {
            for (int t = tid; t < DT * 256; t += 256)
                sW1t[t] = xi_w1[dt * DT * 256 + t];
            __syncthreads();
            #pragma unroll 4
            for (int dd = 0; dd < DT; dd++) {
                int d = dt * DT + dd;
                float4 x0 = *(const float4*)(sXpT + d * 128 + i0);
                float4 x1 = *(const float4*)(sXpT + d * 128 + i0 + 4);
                float4 wa = *(const float4*)(sW1t + dd * 256 + jA);
                float4 wc = *(const float4*)(sW1t + dd * 256 + jA + 128);
                ull wp0 = pk2(wa.x, wa.y), wp1 = pk2(wa.z, wa.w);
                ull wp2 = pk2(wc.x, wc.y), wp3 = pk2(wc.z, wc.w);
                float xv[8] = {x0.x, x0.y, x0.z, x0.w, x1.x, x1.y, x1.z, x1.w};
                #pragma unroll
                for (int r = 0; r < 8; r++) {
                    ull rr = pk2(xv[r], xv[r]);
                    fma2(accp[r][0], rr, wp0);
                    fma2(accp[r][1], rr, wp1);
                    fma2(accp[r][2], rr, wp2);
                    fma2(accp[r][3], rr, wp3);
                }
            }
            __syncthreads();
        }
        #pragma unroll
        for (int r = 0; r < 8; r++) {
            float wi = swxi[i0 + r];
            #pragma unroll
            for (int cp = 0; cp < 4; cp++) {
                float lo, hi;
                upk2(accp[r][cp], lo, hi);
                hbar[cp * 2]     += wi * fmaxf(lo, 0.f);
                hbar[cp * 2 + 1] += wi * fmaxf(hi, 0.f);
            }
        }
    }
    #pragma unroll
    for (int c = 0; c < 4; c++) {
        hpart[wid * 256 + jA + c]       = hbar[c];
        hpart[wid * 256 + jA + 128 + c] = hbar[4 + c];
    }
    __syncthreads();

    int j = tid;
    float hx = 0.f;
    #pragma unroll
    for (int g = 0; g < 8; g++) hx += hpart[g * 256 + j];
    hxs[j] = hx;

    // phi path (diagonal pairs only — typically 0-2 per batch)
    float hp = 0.f;
    int nd = s_nd;
    for (int t = 0; t < nd; t++) {
        int i = dlist[t];
        float acc = phi_b1[j];
        #pragma unroll 8
        for (int d = 0; d < DIM; d++) acc += sXpT[d * 128 + i] * phi_w1[d * HIDN + j];
        hp += sw[i] * fmaxf(acc, 0.f);
    }
    hps[j] = hp;
    __syncthreads();

    // layer-2 folded into pooling
    float out = s_swxi * xi_b2[j];
    #pragma unroll 8
    for (int k = 0; k < HIDN; k++) out += hxs[k] * xi_w2[k * HIDN + j];
    if (nd > 0) {
        out += s_swphi * phi_b2[j];
        #pragma unroll 8
        for (int k = 0; k < HIDN; k++) out += hps[k] * phi_w2[k * HIDN + j];
    }
    g_pooled[b * HIDN + j] = out;
}

// ---------------- kernel F: rho MLP (simple, measured-good) ----------------
__global__ void kRho(const float* __restrict__ w1, const float* __restrict__ b1,
                     const float* __restrict__ w2, const float* __restrict__ b2,
                     float* __restrict__ out) {
    __shared__ float p[HIDN];
    __shared__ float h[HIDN];
    int b = blockIdx.x, tid = threadIdx.x;
    p[tid] = g_pooled[b * HIDN + tid];
    __syncthreads();
    float acc = b1[tid];
    #pragma unroll 8
    for (int k = 0; k < HIDN; k++) acc += p[k] * w1[k * HIDN + tid];
    h[tid] = fmaxf(acc, 0.f);
    __syncthreads();
    if (tid < 128) {
        float o = b2[tid];
        #pragma unroll 8
        for (int k = 0; k < HIDN; k++) o += h[k] * w2[k * 128 + tid];
        out[b * 128 + tid] = o;
    }
}

// ---------------- launch ----------------
extern "C" void kernel_launch(void* const* d_in, const int* in_sizes, int n_in,
                              void* d_out, int out_size) {
    const float* x      = (const float*)d_in[0];
    const float* Wq     = (const float*)d_in[1];
    const float* bq     = (const float*)d_in[2];
    const float* Wk     = (const float*)d_in[3];
    const float* bk     = (const float*)d_in[4];
    const float* phi_w1 = (const float*)d_in[5];
    const float* phi_b1 = (const float*)d_in[6];
    const float* phi_w2 = (const float*)d_in[7];
    const float* phi_b2 = (const float*)d_in[8];
    const float* xi_w1  = (const float*)d_in[9];
    const float* xi_b1  = (const float*)d_in[10];
    const float* xi_w2  = (const float*)d_in[11];
    const float* xi_b2  = (const float*)d_in[12];
    const float* rho_w1 = (const float*)d_in[13];
    const float* rho_b1 = (const float*)d_in[14];
    const float* rho_w2 = (const float*)d_in[15];
    const float* rho_b2 = (const float*)d_in[16];
    float* out = (float*)d_out;

    int stSmem = ST_SMEM_FLOATS * sizeof(float);
    int prSmem = PR_SMEM_FLOATS * sizeof(float);
    cudaFuncSetAttribute(kScoresTopK, cudaFuncAttributeMaxDynamicSharedMemorySize, stSmem);
    cudaFuncSetAttribute(kPairs,      cudaFuncAttributeMaxDynamicSharedMemorySize, prSmem);

    kPrep<<<17, 256>>>(Wq, Wk, bq, bk);
    kScoresTopK<<<BATCH, 256, stSmem>>>(x);
    kPairs<<<BATCH, 256, prSmem>>>(x, xi_w1, xi_b1, xi_w2, xi_b2,
                                   phi_w1, phi_b1, phi_w2, phi_b2);
    kRho<<<BATCH, 256>>>(rho_w1, rho_b1, rho_w2, rho_b2, out);
}

// round 15
// speedup vs baseline: 1.4764x; 1.4764x over previous
#include <cuda_runtime.h>
#include <math.h>

#define BATCH 512
#define LEN   256
#define DIM   64
#define HIDN  256
#define TOPK  128
#define NBINS 2048
#define CAND  1024

typedef unsigned long long ull;

__device__ __forceinline__ ull pk2(float lo, float hi) {
    ull r;
    asm("mov.b64 %0, {%1, %2};" : "=l"(r) : "f"(lo), "f"(hi));
    return r;
}
__device__ __forceinline__ void upk2(ull v, float& lo, float& hi) {
    asm("mov.b64 {%0, %1}, %2;" : "=f"(lo), "=f"(hi) : "l"(v));
}
__device__ __forceinline__ void fma2(ull& d, ull a, ull b) {
    asm("fma.rn.f32x2 %0, %1, %2, %0;" : "+l"(d) : "l"(a), "l"(b));
}

// ---------------- static scratch ----------------
__device__ float g_M[DIM * DIM];
__device__ float g_u[DIM];
__device__ float g_v[DIM];
__device__ float g_cc;
__device__ int   g_rows[BATCH * TOPK];
__device__ int   g_cols[BATCH * TOPK];
__device__ float g_wt[BATCH * TOPK];

// ---------------- kernel A: M = Wq Wk^T, u = Wq bk, v = Wk bq, cc = bq.bk ----
__global__ void kPrep(const float* __restrict__ Wq, const float* __restrict__ Wk,
                      const float* __restrict__ bq, const float* __restrict__ bk) {
    int tid = threadIdx.x;
    if (blockIdx.x < 16) {
        int idx = blockIdx.x * 256 + tid;
        int d  = idx >> 6;
        int dp = idx & 63;
        float acc = 0.f;
        #pragma unroll 8
        for (int h = 0; h < HIDN; h++) acc += Wq[d * HIDN + h] * Wk[dp * HIDN + h];
        g_M[idx] = acc;
    } else {
        if (tid < 64) {
            float a = 0.f;
            for (int h = 0; h < HIDN; h++) a += Wq[tid * HIDN + h] * bk[h];
            g_u[tid] = a;
        } else if (tid < 128) {
            int d = tid - 64;
            float a = 0.f;
            for (int h = 0; h < HIDN; h++) a += Wk[d * HIDN + h] * bq[h];
            g_v[d] = a;
        } else if (tid == 128) {
            float a = 0.f;
            for (int h = 0; h < HIDN; h++) a += bq[h] * bk[h];
            g_cc = a;
        }
    }
}

// ---------------- fused: scores + exact top-128 + softmax, 2 CTAs/SM ----------
// (R12 measured-good version: bitonic sort selection)
#define ST_SMEM_FLOATS (16640 + 4096 + 256 + 256 + 2048 + 128 + 1024 + 1024 + 16)
__global__ __launch_bounds__(256, 2) void kScoresTopK(const float* __restrict__ x) {
    extern __shared__ float sm[];
    float* sX   = sm;                 // [64 d][260]
    float* sGw  = sX + 16640;         // per-warp: [8w][64 d][8 r]
    float* sA   = sGw + 4096;         // 256
    float* sC   = sA + 256;           // 256
    unsigned int* hist = (unsigned int*)(sC + 256);      // 2048
    unsigned int* scan = hist + NBINS;                    // 128
    float* cvals = (float*)(scan + 128);                  // 1024
    int*   cidx  = (int*)(cvals + CAND);                  // 1024
    float* wred  = (float*)(cidx + CAND);                 // 16
    __shared__ unsigned int s_cnt;
    __shared__ int s_cb;
    __shared__ float s_thr, s_minv, s_binw;
    __shared__ float sred[128];

    int b = blockIdx.x, tid = threadIdx.x;
    int lane = tid & 31, wid = tid >> 5;   // wid 0..7
    const float* xb = x + (size_t)b * LEN * DIM;
    float* sGwW = sGw + wid * 512;         // this warp's [64 d][8 r] tile

    // load x^T: sX[d][m] = x[m][d]
    for (int t = tid; t < LEN * DIM; t += 256) {
        int m = t >> 6, d = t & 63;
        sX[d * 260 + m] = xb[m * DIM + d];
    }
    if (tid == 0) s_cnt = 0u;
    __syncthreads();

    // bias rows
    {
        int l = tid;
        float a = 0.f, c = 0.f;
        #pragma unroll 8
        for (int d = 0; d < DIM; d++) {
            float xv = sX[d * 260 + l];
            a += xv * g_u[d];
            c += xv * g_v[d];
        }
        sA[l] = a; sC[l] = c;
    }
    float ccv = g_cc;
    __syncthreads();

    const float scale = 0.0625f;   // 256^-0.5
    int mA = lane * 4;             // cols mA..+3 and mA+128..+131

    for (int chunk = 0; chunk < 4; chunk++) {
        int l0 = chunk * 64 + wid * 8;

        // ---- per-warp G tile: Gw[d][r] = sum_dd x[l0+r][dd] * M[dd][d] ----
        {
            float acc2[8][2];
            #pragma unroll
            for (int r = 0; r < 8; r++) { acc2[r][0] = 0.f; acc2[r][1] = 0.f; }
            #pragma unroll 4
            for (int dd = 0; dd < DIM; dd++) {
                float4 xq0 = *(const float4*)(sX + dd * 260 + l0);      // broadcast
                float4 xq1 = *(const float4*)(sX + dd * 260 + l0 + 4);
                float m0 = g_M[dd * 64 + lane];
                float m1 = g_M[dd * 64 + lane + 32];
                float xv[8] = {xq0.x, xq0.y, xq0.z, xq0.w, xq1.x, xq1.y, xq1.z, xq1.w};
                #pragma unroll
                for (int r = 0; r < 8; r++) {
                    acc2[r][0] += xv[r] * m0;
                    acc2[r][1] += xv[r] * m1;
                }
            }
            #pragma unroll
            for (int r = 0; r < 8; r++) {
                sGwW[lane * 8 + r]        = acc2[r][0];
                sGwW[(lane + 32) * 8 + r] = acc2[r][1];
            }
            __syncwarp();
        }

        // ---- GEMM 8x8 tile, f32x2 packed ----
        ull accp[8][4];
        #pragma unroll
        for (int r = 0; r < 8; r++)
            #pragma unroll
            for (int c = 0; c < 4; c++) accp[r][c] = 0ull;

        #pragma unroll 4
        for (int d = 0; d < DIM; d++) {
            float4 g0 = *(const float4*)(sGwW + d * 8);       // broadcast
            float4 g1 = *(const float4*)(sGwW + d * 8 + 4);
            float4 xa = *(const float4*)(sX + d * 260 + mA);
            float4 xc = *(const float4*)(sX + d * 260 + mA + 128);
            ull xp0 = pk2(xa.x, xa.y), xp1 = pk2(xa.z, xa.w);
            ull xp2 = pk2(xc.x, xc.y), xp3 = pk2(xc.z, xc.w);
            float gv[8] = {g0.x, g0.y, g0.z, g0.w, g1.x, g1.y, g1.z, g1.w};
            #pragma unroll
            for (int r = 0; r < 8; r++) {
                ull rr = pk2(gv[r], gv[r]);
                fma2(accp[r][0], rr, xp0);
                fma2(accp[r][1], rr, xp1);
                fma2(accp[r][2], rr, xp2);
                fma2(accp[r][3], rr, xp3);
            }
        }

        // epilogue: bias + scale, repack into accp, min/max
        float lmin = 3.4e38f, lmax = -3.4e38f;
        #pragma unroll
        for (int r = 0; r < 8; r++) {
            float base = sA[l0 + r] + ccv;
            #pragma unroll
            for (int cp = 0; cp < 4; cp++) {
                float lo, hi;
                upk2(accp[r][cp], lo, hi);
                int c0 = cp * 2;
                int m0 = (c0 < 4) ? (mA + c0) : (mA + 124 + c0);
                float v0 = scale * (lo + base + sC[m0]);
                float v1 = scale * (hi + base + sC[m0 + 1]);
                accp[r][cp] = pk2(v0, v1);
                lmin = fminf(lmin, fminf(v0, v1));
                lmax = fmaxf(lmax, fmaxf(v0, v1));
            }
        }
        #pragma unroll
        for (int o = 16; o > 0; o >>= 1) {
            lmin = fminf(lmin, __shfl_xor_sync(0xffffffffu, lmin, o));
            lmax = fmaxf(lmax, __shfl_xor_sync(0xffffffffu, lmax, o));
        }
        if (lane == 0) { wred[wid] = lmin; wred[8 + wid] = lmax; }
        for (int t = tid; t < NBINS; t += 256) hist[t] = 0u;
        __syncthreads();
        if (tid == 0) {
            float mn = wred[0], mx = wred[8];
            #pragma unroll
            for (int w = 1; w < 8; w++) {
                mn = fminf(mn, wred[w]);
                mx = fmaxf(mx, wred[8 + w]);
            }
            float range = fmaxf(mx - mn, 1e-20f);
            s_minv = mn;
            s_binw = range / (float)NBINS;
        }
        __syncthreads();
        float minv = s_minv;
        float invw = 1.0f / s_binw;

        // histogram from packed registers
        #pragma unroll
        for (int r = 0; r < 8; r++)
            #pragma unroll
            for (int cp = 0; cp < 4; cp++) {
                float lo, hi;
                upk2(accp[r][cp], lo, hi);
                int b0 = (int)((lo - minv) * invw);
                int b1 = (int)((hi - minv) * invw);
                b0 = min(max(b0, 0), NBINS - 1);
                b1 = min(max(b1, 0), NBINS - 1);
                atomicAdd(&hist[b0], 1u);
                atomicAdd(&hist[b1], 1u);
            }
        __syncthreads();

        // coarse sums (16 bins each) + Kogge-Stone suffix sum over 128 groups
        if (tid < 128) {
            unsigned int s = 0;
            #pragma unroll
            for (int k = 0; k < 16; k++) s += hist[tid * 16 + k];
            scan[tid] = s;
        }
        __syncthreads();
        for (int off = 1; off < 128; off <<= 1) {
            unsigned int add = 0;
            if (tid < 128 && tid + off < 128) add = scan[tid + off];
            __syncthreads();
            if (tid < 128) scan[tid] += add;
            __syncthreads();
        }
        if (tid < 128) {
            unsigned int sfx = scan[tid];
            unsigned int nxt = (tid < 127) ? scan[tid + 1] : 0u;
            if (sfx >= TOPK && nxt < TOPK) s_cb = tid;
        }
        __syncthreads();
        if (tid == 0) {
            int cb = s_cb;
            unsigned int cum = (cb < 127) ? scan[cb + 1] : 0u;
            int tbin = cb * 16;
            for (int f = cb * 16 + 15; f >= cb * 16; f--) {
                cum += hist[f];
                if (cum >= TOPK) { tbin = f; break; }
            }
            int tc = max(tbin - 1, 0);     // one-bin safety margin
            s_thr = minv + (float)tc * s_binw;
        }
        __syncthreads();
        float thr = s_thr;

        // collect candidates from packed registers
        #pragma unroll
        for (int r = 0; r < 8; r++)
            #pragma unroll
            for (int cp = 0; cp < 4; cp++) {
                float lo, hi;
                upk2(accp[r][cp], lo, hi);
                int c0 = cp * 2;
                int m0 = (c0 < 4) ? (mA + c0) : (mA + 124 + c0);
                if (lo >= thr) {
                    unsigned int p = atomicAdd(&s_cnt, 1u);
                    if (p < CAND) { cvals[p] = lo; cidx[p] = (l0 + r) * LEN + m0; }
                }
                if (hi >= thr) {
                    unsigned int p = atomicAdd(&s_cnt, 1u);
                    if (p < CAND) { cvals[p] = hi; cidx[p] = (l0 + r) * LEN + m0 + 1; }
                }
            }
        __syncthreads();
    }

    // pad + bitonic sort (descending)
    int C = (int)min(s_cnt, (unsigned int)CAND);
    for (int t = C + tid; t < CAND; t += 256) { cvals[t] = -3.4e38f; cidx[t] = 0; }
    __syncthreads();
    for (int k = 2; k <= CAND; k <<= 1) {
        for (int j = k >> 1; j > 0; j >>= 1) {
            for (int i = tid; i < CAND; i += 256) {
                int ixj = i ^ j;
                if (ixj > i) {
                    float vi = cvals[i], vj = cvals[ixj];
                    bool descBlock = ((i & k) == 0);
                    if (descBlock ? (vi < vj) : (vi > vj)) {
                        cvals[i] = vj; cvals[ixj] = vi;
                        int t2 = cidx[i]; cidx[i] = cidx[ixj]; cidx[ixj] = t2;
                    }
                }
            }
            __syncthreads();
        }
    }

    // softmax over top-128
    float maxval = cvals[0];
    float e = 0.f;
    if (tid < TOPK) { e = expf(cvals[tid] - maxval); sred[tid] = e; }
    __syncthreads();
    for (int s = 64; s > 0; s >>= 1) {
        if (tid < s) sred[tid] += sred[tid + s];
        __syncthreads();
    }
    float denom = sred[0];
    if (tid < TOPK) {
        int idx = cidx[tid];
        g_rows[b * TOPK + tid] = idx >> 8;
        g_cols[b * TOPK + tid] = idx & 255;
        g_wt[b * TOPK + tid]   = e / denom;
    }
}

// ---------------- kernel E: pair features + pool + layer2 + rho (fused) ----
// smem floats: sW1t 8192 + sXpT 16384 + hpart 2048 + hxs 256 + hps 256 + misc 640
#define PR_SMEM_FLOATS (8192 + 16384 + 2048 + 256 + 256 + 128 + 128 + 128 + 128 + 128)
#define DT 32
__global__ __launch_bounds__(256, 2) void kPairs(const float* __restrict__ x,
                       const float* __restrict__ xi_w1, const float* __restrict__ xi_b1,
                       const float* __restrict__ xi_w2, const float* __restrict__ xi_b2,
                       const float* __restrict__ phi_w1, const float* __restrict__ phi_b1,
                       const float* __restrict__ phi_w2, const float* __restrict__ phi_b2,
                       const float* __restrict__ rho_w1, const float* __restrict__ rho_b1,
                       const float* __restrict__ rho_w2, const float* __restrict__ rho_b2,
                       float* __restrict__ outp) {
    extern __shared__ float sm[];
    float* sW1t  = sm;                    // [32 d][256 j] tile
    float* sXpT  = sW1t + 8192;           // [128 d][128 i]
    float* hpart = sXpT + 16384;          // [8][256]; later reused: [0,256)=pooled, [256,512)=rho h
    float* hxs   = hpart + 2048;          // 256
    float* hps   = hxs + 256;             // 256
    float* sw    = hps + 256;             // 128
    float* swxi  = sw + 128;              // 128
    int* srow  = (int*)(swxi + 128);      // 128
    int* scol  = srow + 128;              // 128
    int* dlist = scol + 128;              // 128
    __shared__ int   s_nd;
    __shared__ float s_swxi, s_swphi;

    int b = blockIdx.x, tid = threadIdx.x;
    int lane = tid & 31, wid = tid >> 5;  // wid 0..7

    if (tid < TOPK) {
        srow[tid] = g_rows[b * TOPK + tid];
        scol[tid] = g_cols[b * TOPK + tid];
        sw[tid]   = g_wt[b * TOPK + tid];
    }
    __syncthreads();

    // transposed pair matrix: rows 0..63 = x_row dims, 64..127 = x_col dims
    {
        int i = tid >> 1, half = tid & 1;
        int src = half ? scol[i] : srow[i];
        const float* xr = x + ((size_t)b * LEN + src) * DIM;
        #pragma unroll
        for (int dv = 0; dv < 16; dv++) {
            float4 v = *(const float4*)(xr + dv * 4);
            int d = half * 64 + dv * 4;
            sXpT[(d + 0) * 128 + i] = v.x;
            sXpT[(d + 1) * 128 + i] = v.y;
            sXpT[(d + 2) * 128 + i] = v.z;
            sXpT[(d + 3) * 128 + i] = v.w;
        }
    }
    if (tid == 0) {
        int nd = 0; float sphi = 0.f, sxi = 0.f;
        for (int i = 0; i < TOPK; i++) {
            if (srow[i] == scol[i]) { dlist[nd++] = i; sphi += sw[i]; }
            else sxi += sw[i];
        }
        s_nd = nd; s_swphi = sphi; s_swxi = sxi;
    }
    if (tid < TOPK) swxi[tid] = (srow[tid] == scol[tid]) ? 0.f : sw[tid];
    __syncthreads();

    // xi layer-1: f32x2 packed 8x8 tile, W1 streamed in 32-row d-tiles
    int jA = lane * 4;
    float4 b1a = *(const float4*)(xi_b1 + jA);
    float4 b1c = *(const float4*)(xi_b1 + jA + 128);
    ull bp0 = pk2(b1a.x, b1a.y), bp1 = pk2(b1a.z, b1a.w);
    ull bp2 = pk2(b1c.x, b1c.y), bp3 = pk2(b1c.z, b1c.w);
    float hbar[8] = {0.f, 0.f, 0.f, 0.f, 0.f, 0.f, 0.f, 0.f};

    for (int iter = 0; iter < 2; iter++) {
        int i0 = wid * 8 + iter * 64;  // warp-uniform i tile
        ull accp[8][4];
        #pragma unroll
        for (int r = 0; r < 8; r++) {
            accp[r][0] = bp0; accp[r][1] = bp1; accp[r][2] = bp2; accp[r][3] = bp3;
        }
        for (int dt = 0; dt < 128 / DT; dt++) {
            for (int t = tid; t < DT * 256; t += 256)
                sW1t[t] = xi_w1[dt * DT * 256 + t];
            __syncthreads();
            #pragma unroll 4
            for (int dd = 0; dd < DT; dd++) {
                int d = dt * DT + dd;
                float4 x0 = *(const float4*)(sXpT + d * 128 + i0);
                float4 x1 = *(const float4*)(sXpT + d * 128 + i0 + 4);
                float4 wa = *(const float4*)(sW1t + dd * 256 + jA);
                float4 wc = *(const float4*)(sW1t + dd * 256 + jA + 128);
                ull wp0 = pk2(wa.x, wa.y), wp1 = pk2(wa.z, wa.w);
                ull wp2 = pk2(wc.x, wc.y), wp3 = pk2(wc.z, wc.w);
                float xv[8] = {x0.x, x0.y, x0.z, x0.w, x1.x, x1.y, x1.z, x1.w};
                #pragma unroll
                for (int r = 0; r < 8; r++) {
                    ull rr = pk2(xv[r], xv[r]);
                    fma2(accp[r][0], rr, wp0);
                    fma2(accp[r][1], rr, wp1);
                    fma2(accp[r][2], rr, wp2);
                    fma2(accp[r][3], rr, wp3);
                }
            }
            __syncthreads();
        }
        #pragma unroll
        for (int r = 0; r < 8; r++) {
            float wi = swxi[i0 + r];
            #pragma unroll
            for (int cp = 0; cp < 4; cp++) {
                float lo, hi;
                upk2(accp[r][cp], lo, hi);
                hbar[cp * 2]     += wi * fmaxf(lo, 0.f);
                hbar[cp * 2 + 1] += wi * fmaxf(hi, 0.f);
            }
        }
    }
    #pragma unroll
    for (int c = 0; c < 4; c++) {
        hpart[wid * 256 + jA + c]       = hbar[c];
        hpart[wid * 256 + jA + 128 + c] = hbar[4 + c];
    }
    __syncthreads();

    int j = tid;
    float hx = 0.f;
    #pragma unroll
    for (int g = 0; g < 8; g++) hx += hpart[g * 256 + j];
    hxs[j] = hx;

    // phi path (diagonal pairs only — typically 0-2 per batch)
    float hp = 0.f;
    int nd = s_nd;
    for (int t = 0; t < nd; t++) {
        int i = dlist[t];
        float acc = phi_b1[j];
        #pragma unroll 8
        for (int d = 0; d < DIM; d++) acc += sXpT[d * 128 + i] * phi_w1[d * HIDN + j];
        hp += sw[i] * fmaxf(acc, 0.f);
    }
    hps[j] = hp;
    __syncthreads();

    // layer-2 folded into pooling -> pooled[j], stored in hpart[0..255]
    {
        float out = s_swxi * xi_b2[j];
        #pragma unroll 8
        for (int k = 0; k < HIDN; k++) out += hxs[k] * xi_w2[k * HIDN + j];
        if (nd > 0) {
            out += s_swphi * phi_b2[j];
            #pragma unroll 8
            for (int k = 0; k < HIDN; k++) out += hps[k] * phi_w2[k * HIDN + j];
        }
        hpart[j] = out;             // pooled
    }
    __syncthreads();

    // rho layer-1: h[j] = relu(b1[j] + sum_k pooled[k]*w1[k][j]) -> hpart[256..511]
    {
        float acc = rho_b1[j];
        #pragma unroll 8
        for (int k = 0; k < HIDN; k++) acc += hpart[k] * rho_w1[k * HIDN + j];
        hpart[256 + j] = fmaxf(acc, 0.f);
    }
    __syncthreads();

    // rho layer-2: out[b][j] for j < 128
    if (tid < 128) {
        float o = rho_b2[tid];
        #pragma unroll 8
        for (int k = 0; k < HIDN; k++) o += hpart[256 + k] * rho_w2[k * 128 + tid];
        outp[b * 128 + tid] = o;
    }
}

// ---------------- launch ----------------
extern "C" void kernel_launch(void* const* d_in, const int* in_sizes, int n_in,
                              void* d_out, int out_size) {
    const float* x      = (const float*)d_in[0];
    const float* Wq     = (const float*)d_in[1];
    const float* bq     = (const float*)d_in[2];
    const float* Wk     = (const float*)d_in[3];
    const float* bk     = (const float*)d_in[4];
    const float* phi_w1 = (const float*)d_in[5];
    const float* phi_b1 = (const float*)d_in[6];
    const float* phi_w2 = (const float*)d_in[7];
    const float* phi_b2 = (const float*)d_in[8];
    const float* xi_w1  = (const float*)d_in[9];
    const float* xi_b1  = (const float*)d_in[10];
    const float* xi_w2  = (const float*)d_in[11];
    const float* xi_b2  = (const float*)d_in[12];
    const float* rho_w1 = (const float*)d_in[13];
    const float* rho_b1 = (const float*)d_in[14];
    const float* rho_w2 = (const float*)d_in[15];
    const float* rho_b2 = (const float*)d_in[16];
    float* out = (float*)d_out;

    int stSmem = ST_SMEM_FLOATS * sizeof(float);
    int prSmem = PR_SMEM_FLOATS * sizeof(float);
    cudaFuncSetAttribute(kScoresTopK, cudaFuncAttributeMaxDynamicSharedMemorySize, stSmem);
    cudaFuncSetAttribute(kPairs,      cudaFuncAttributeMaxDynamicSharedMemorySize, prSmem);

    kPrep<<<17, 256>>>(Wq, Wk, bq, bk);
    kScoresTopK<<<BATCH, 256, stSmem>>>(x);
    kPairs<<<BATCH, 256, prSmem>>>(x, xi_w1, xi_b1, xi_w2, xi_b2,
                                   phi_w1, phi_b1, phi_w2, phi_b2,
                                   rho_w1, rho_b1, rho_w2, rho_b2, out);
}

// round 16
// speedup vs baseline: 1.5854x; 1.0738x over previous
#include <cuda_runtime.h>
#include <math.h>

#define BATCH 512
#define LEN   256
#define DIM   64
#define HIDN  256
#define TOPK  128
#define NBINS 2048
#define CAND  1024

typedef unsigned long long ull;

__device__ __forceinline__ ull pk2(float lo, float hi) {
    ull r;
    asm("mov.b64 %0, {%1, %2};" : "=l"(r) : "f"(lo), "f"(hi));
    return r;
}
__device__ __forceinline__ void upk2(ull v, float& lo, float& hi) {
    asm("mov.b64 {%0, %1}, %2;" : "=f"(lo), "=f"(hi) : "l"(v));
}
__device__ __forceinline__ void fma2(ull& d, ull a, ull b) {
    asm("fma.rn.f32x2 %0, %1, %2, %0;" : "+l"(d) : "l"(a), "l"(b));
}

// ---------------- static scratch ----------------
__device__ float g_M[DIM * DIM];
__device__ float g_u[DIM];
__device__ float g_v[DIM];
__device__ float g_cc;
__device__ int   g_rows[BATCH * TOPK];
__device__ int   g_cols[BATCH * TOPK];
__device__ float g_wt[BATCH * TOPK];

// ---------------- kernel A: warp-per-output prep ----------------
// blocks 0..511:   M[idx], idx = blockIdx.x*8 + warp   (4096 outputs)
// blocks 512..528: u (0..63), v (64..127), cc (128)    (129 outputs)
__global__ void kPrep(const float* __restrict__ Wq, const float* __restrict__ Wk,
                      const float* __restrict__ bq, const float* __restrict__ bk) {
    int lane = threadIdx.x & 31, wid = threadIdx.x >> 5;
    if (blockIdx.x < 512) {
        int idx = blockIdx.x * 8 + wid;
        int d  = idx >> 6;
        int dp = idx & 63;
        const float4* q4 = (const float4*)(Wq + d * HIDN + lane * 8);
        const float4* k4 = (const float4*)(Wk + dp * HIDN + lane * 8);
        float4 qa = q4[0], qb = q4[1];
        float4 ka = k4[0], kb = k4[1];
        float acc = qa.x * ka.x + qa.y * ka.y + qa.z * ka.z + qa.w * ka.w
                  + qb.x * kb.x + qb.y * kb.y + qb.z * kb.z + qb.w * kb.w;
        #pragma unroll
        for (int o = 16; o > 0; o >>= 1)
            acc += __shfl_down_sync(0xffffffffu, acc, o);
        if (lane == 0) g_M[idx] = acc;
    } else {
        int w = (blockIdx.x - 512) * 8 + wid;   // 0..135
        if (w < 129) {
            const float* a;
            const float* bvec;
            if (w < 64)       { a = Wq + w * HIDN;        bvec = bk; }
            else if (w < 128) { a = Wk + (w - 64) * HIDN; bvec = bq; }
            else              { a = bq;                   bvec = bk; }
            const float4* a4 = (const float4*)(a + lane * 8);
            const float4* b4 = (const float4*)(bvec + lane * 8);
            float4 aa = a4[0], ab = a4[1];
            float4 ba = b4[0], bb = b4[1];
            float acc = aa.x * ba.x + aa.y * ba.y + aa.z * ba.z + aa.w * ba.w
                      + ab.x * bb.x + ab.y * bb.y + ab.z * bb.z + ab.w * bb.w;
            #pragma unroll
            for (int o = 16; o > 0; o >>= 1)
                acc += __shfl_down_sync(0xffffffffu, acc, o);
            if (lane == 0) {
                if (w < 64)       g_u[w] = acc;
                else if (w < 128) g_v[w - 64] = acc;
                else              g_cc = acc;
            }
        }
    }
}

// ---------------- fused: scores + exact top-128 + softmax, 2 CTAs/SM ----------
#define ST_SMEM_FLOATS (16640 + 4096 + 256 + 256 + 2048 + 128 + 1024 + 1024 + 16)
__global__ __launch_bounds__(256, 2) void kScoresTopK(const float* __restrict__ x) {
    extern __shared__ float sm[];
    float* sX   = sm;                 // [64 d][260]
    float* sGw  = sX + 16640;         // per-warp: [8w][64 d][8 r]
    float* sA   = sGw + 4096;         // 256
    float* sC   = sA + 256;           // 256
    unsigned int* hist = (unsigned int*)(sC + 256);      // 2048
    unsigned int* scan = hist + NBINS;                    // 128
    float* cvals = (float*)(scan + 128);                  // 1024
    int*   cidx  = (int*)(cvals + CAND);                  // 1024
    float* wred  = (float*)(cidx + CAND);                 // 16
    __shared__ unsigned int s_cnt;
    __shared__ int s_cb;
    __shared__ float s_thr, s_minv, s_binw;
    __shared__ float sred[128];

    int b = blockIdx.x, tid = threadIdx.x;
    int lane = tid & 31, wid = tid >> 5;   // wid 0..7
    const float* xb = x + (size_t)b * LEN * DIM;
    float* sGwW = sGw + wid * 512;         // this warp's [64 d][8 r] tile

    // load x^T: sX[d][m] = x[m][d]
    for (int t = tid; t < LEN * DIM; t += 256) {
        int m = t >> 6, d = t & 63;
        sX[d * 260 + m] = xb[m * DIM + d];
    }
    if (tid == 0) s_cnt = 0u;
    __syncthreads();

    // bias rows
    {
        int l = tid;
        float a = 0.f, c = 0.f;
        #pragma unroll 8
        for (int d = 0; d < DIM; d++) {
            float xv = sX[d * 260 + l];
            a += xv * g_u[d];
            c += xv * g_v[d];
        }
        sA[l] = a; sC[l] = c;
    }
    float ccv = g_cc;
    __syncthreads();

    const float scale = 0.0625f;   // 256^-0.5
    int mA = lane * 4;             // cols mA..+3 and mA+128..+131

    for (int chunk = 0; chunk < 4; chunk++) {
        int l0 = chunk * 64 + wid * 8;

        // ---- per-warp G tile: Gw[d][r] = sum_dd x[l0+r][dd] * M[dd][d] ----
        {
            float acc2[8][2];
            #pragma unroll
            for (int r = 0; r < 8; r++) { acc2[r][0] = 0.f; acc2[r][1] = 0.f; }
            #pragma unroll 4
            for (int dd = 0; dd < DIM; dd++) {
                float4 xq0 = *(const float4*)(sX + dd * 260 + l0);      // broadcast
                float4 xq1 = *(const float4*)(sX + dd * 260 + l0 + 4);
                float m0 = g_M[dd * 64 + lane];
                float m1 = g_M[dd * 64 + lane + 32];
                float xv[8] = {xq0.x, xq0.y, xq0.z, xq0.w, xq1.x, xq1.y, xq1.z, xq1.w};
                #pragma unroll
                for (int r = 0; r < 8; r++) {
                    acc2[r][0] += xv[r] * m0;
                    acc2[r][1] += xv[r] * m1;
                }
            }
            #pragma unroll
            for (int r = 0; r < 8; r++) {
                sGwW[lane * 8 + r]        = acc2[r][0];
                sGwW[(lane + 32) * 8 + r] = acc2[r][1];
            }
            __syncwarp();
        }

        // ---- GEMM 8x8 tile, f32x2 packed ----
        ull accp[8][4];
        #pragma unroll
        for (int r = 0; r < 8; r++)
            #pragma unroll
            for (int c = 0; c < 4; c++) accp[r][c] = 0ull;

        #pragma unroll 4
        for (int d = 0; d < DIM; d++) {
            float4 g0 = *(const float4*)(sGwW + d * 8);       // broadcast
            float4 g1 = *(const float4*)(sGwW + d * 8 + 4);
            float4 xa = *(const float4*)(sX + d * 260 + mA);
            float4 xc = *(const float4*)(sX + d * 260 + mA + 128);
            ull xp0 = pk2(xa.x, xa.y), xp1 = pk2(xa.z, xa.w);
            ull xp2 = pk2(xc.x, xc.y), xp3 = pk2(xc.z, xc.w);
            float gv[8] = {g0.x, g0.y, g0.z, g0.w, g1.x, g1.y, g1.z, g1.w};
            #pragma unroll
            for (int r = 0; r < 8; r++) {
                ull rr = pk2(gv[r], gv[r]);
                fma2(accp[r][0], rr, xp0);
                fma2(accp[r][1], rr, xp1);
                fma2(accp[r][2], rr, xp2);
                fma2(accp[r][3], rr, xp3);
            }
        }

        // epilogue: bias + scale, repack into accp, min/max
        float lmin = 3.4e38f, lmax = -3.4e38f;
        #pragma unroll
        for (int r = 0; r < 8; r++) {
            float base = sA[l0 + r] + ccv;
            #pragma unroll
            for (int cp = 0; cp < 4; cp++) {
                float lo, hi;
                upk2(accp[r][cp], lo, hi);
                int c0 = cp * 2;
                int m0 = (c0 < 4) ? (mA + c0) : (mA + 124 + c0);
                float v0 = scale * (lo + base + sC[m0]);
                float v1 = scale * (hi + base + sC[m0 + 1]);
                accp[r][cp] = pk2(v0, v1);
                lmin = fminf(lmin, fminf(v0, v1));
                lmax = fmaxf(lmax, fmaxf(v0, v1));
            }
        }
        #pragma unroll
        for (int o = 16; o > 0; o >>= 1) {
            lmin = fminf(lmin, __shfl_xor_sync(0xffffffffu, lmin, o));
            lmax = fmaxf(lmax, __shfl_xor_sync(0xffffffffu, lmax, o));
        }
        if (lane == 0) { wred[wid] = lmin; wred[8 + wid] = lmax; }
        for (int t = tid; t < NBINS; t += 256) hist[t] = 0u;
        __syncthreads();
        if (tid == 0) {
            float mn = wred[0], mx = wred[8];
            #pragma unroll
            for (int w = 1; w < 8; w++) {
                mn = fminf(mn, wred[w]);
                mx = fmaxf(mx, wred[8 + w]);
            }
            float range = fmaxf(mx - mn, 1e-20f);
            s_minv = mn;
            s_binw = range / (float)NBINS;
        }
        __syncthreads();
        float minv = s_minv;
        float invw = 1.0f / s_binw;

        // histogram from packed registers
        #pragma unroll
        for (int r = 0; r < 8; r++)
            #pragma unroll
            for (int cp = 0; cp < 4; cp++) {
                float lo, hi;
                upk2(accp[r][cp], lo, hi);
                int b0 = (int)((lo - minv) * invw);
                int b1 = (int)((hi - minv) * invw);
                b0 = min(max(b0, 0), NBINS - 1);
                b1 = min(max(b1, 0), NBINS - 1);
                atomicAdd(&hist[b0], 1u);
                atomicAdd(&hist[b1], 1u);
            }
        __syncthreads();

        // coarse sums (16 bins each) + Kogge-Stone suffix sum over 128 groups
        if (tid < 128) {
            unsigned int s = 0;
            #pragma unroll
            for (int k = 0; k < 16; k++) s += hist[tid * 16 + k];
            scan[tid] = s;
        }
        __syncthreads();
        for (int off = 1; off < 128; off <<= 1) {
            unsigned int add = 0;
            if (tid < 128 && tid + off < 128) add = scan[tid + off];
            __syncthreads();
            if (tid < 128) scan[tid] += add;
            __syncthreads();
        }
        if (tid < 128) {
            unsigned int sfx = scan[tid];
            unsigned int nxt = (tid < 127) ? scan[tid + 1] : 0u;
            if (sfx >= TOPK && nxt < TOPK) s_cb = tid;
        }
        __syncthreads();
        if (tid == 0) {
            int cb = s_cb;
            unsigned int cum = (cb < 127) ? scan[cb + 1] : 0u;
            int tbin = cb * 16;
            for (int f = cb * 16 + 15; f >= cb * 16; f--) {
                cum += hist[f];
                if (cum >= TOPK) { tbin = f; break; }
            }
            int tc = max(tbin - 1, 0);     // one-bin safety margin
            s_thr = minv + (float)tc * s_binw;
        }
        __syncthreads();
        float thr = s_thr;

        // collect candidates from packed registers
        #pragma unroll
        for (int r = 0; r < 8; r++)
            #pragma unroll
            for (int cp = 0; cp < 4; cp++) {
                float lo, hi;
                upk2(accp[r][cp], lo, hi);
                int c0 = cp * 2;
                int m0 = (c0 < 4) ? (mA + c0) : (mA + 124 + c0);
                if (lo >= thr) {
                    unsigned int p = atomicAdd(&s_cnt, 1u);
                    if (p < CAND) { cvals[p] = lo; cidx[p] = (l0 + r) * LEN + m0; }
                }
                if (hi >= thr) {
                    unsigned int p = atomicAdd(&s_cnt, 1u);
                    if (p < CAND) { cvals[p] = hi; cidx[p] = (l0 + r) * LEN + m0 + 1; }
                }
            }
        __syncthreads();
    }

    // pad + bitonic sort (descending)
    int C = (int)min(s_cnt, (unsigned int)CAND);
    for (int t = C + tid; t < CAND; t += 256) { cvals[t] = -3.4e38f; cidx[t] = 0; }
    __syncthreads();
    for (int k = 2; k <= CAND; k <<= 1) {
        for (int j = k >> 1; j > 0; j >>= 1) {
            for (int i = tid; i < CAND; i += 256) {
                int ixj = i ^ j;
                if (ixj > i) {
                    float vi = cvals[i], vj = cvals[ixj];
                    bool descBlock = ((i & k) == 0);
                    if (descBlock ? (vi < vj) : (vi > vj)) {
                        cvals[i] = vj; cvals[ixj] = vi;
                        int t2 = cidx[i]; cidx[i] = cidx[ixj]; cidx[ixj] = t2;
                    }
                }
            }
            __syncthreads();
        }
    }

    // softmax over top-128
    float maxval = cvals[0];
    float e = 0.f;
    if (tid < TOPK) { e = expf(cvals[tid] - maxval); sred[tid] = e; }
    __syncthreads();
    for (int s = 64; s > 0; s >>= 1) {
        if (tid < s) sred[tid] += sred[tid + s];
        __syncthreads();
    }
    float denom = sred[0];
    if (tid < TOPK) {
        int idx = cidx[tid];
        g_rows[b * TOPK + tid] = idx >> 8;
        g_cols[b * TOPK + tid] = idx & 255;
        g_wt[b * TOPK + tid]   = e / denom;
    }
}

// ---------------- kernel E: pair features + pool + layer2 + rho (fused) ----
#define PR_SMEM_FLOATS (8192 + 16384 + 2048 + 256 + 256 + 128 + 128 + 128 + 128 + 128)
#define DT 32
__global__ __launch_bounds__(256, 2) void kPairs(const float* __restrict__ x,
                       const float* __restrict__ xi_w1, const float* __restrict__ xi_b1,
                       const float* __restrict__ xi_w2, const float* __restrict__ xi_b2,
                       const float* __restrict__ phi_w1, const float* __restrict__ phi_b1,
                       const float* __restrict__ phi_w2, const float* __restrict__ phi_b2,
                       const float* __restrict__ rho_w1, const float* __restrict__ rho_b1,
                       const float* __restrict__ rho_w2, const float* __restrict__ rho_b2,
                       float* __restrict__ outp) {
    extern __shared__ float sm[];
    float* sW1t  = sm;                    // [32 d][256 j] tile
    float* sXpT  = sW1t + 8192;           // [128 d][128 i]
    float* hpart = sXpT + 16384;          // [8][256]; later reused: [0,256)=pooled, [256,512)=rho h
    float* hxs   = hpart + 2048;          // 256
    float* hps   = hxs + 256;             // 256
    float* sw    = hps + 256;             // 128
    float* swxi  = sw + 128;              // 128
    int* srow  = (int*)(swxi + 128);      // 128
    int* scol  = srow + 128;              // 128
    int* dlist = scol + 128;              // 128
    __shared__ int   s_nd;
    __shared__ float s_swxi, s_swphi;

    int b = blockIdx.x, tid = threadIdx.x;
    int lane = tid & 31, wid = tid >> 5;  // wid 0..7

    if (tid < TOPK) {
        srow[tid] = g_rows[b * TOPK + tid];
        scol[tid] = g_cols[b * TOPK + tid];
        sw[tid]   = g_wt[b * TOPK + tid];
    }
    __syncthreads();

    // transposed pair matrix: rows 0..63 = x_row dims, 64..127 = x_col dims
    {
        int i = tid >> 1, half = tid & 1;
        int src = half ? scol[i] : srow[i];
        const float* xr = x + ((size_t)b * LEN + src) * DIM;
        #pragma unroll
        for (int dv = 0; dv < 16; dv++) {
            float4 v = *(const float4*)(xr + dv * 4);
            int d = half * 64 + dv * 4;
            sXpT[(d + 0) * 128 + i] = v.x;
            sXpT[(d + 1) * 128 + i] = v.y;
            sXpT[(d + 2) * 128 + i] = v.z;
            sXpT[(d + 3) * 128 + i] = v.w;
        }
    }
    if (tid == 0) {
        int nd = 0; float sphi = 0.f, sxi = 0.f;
        for (int i = 0; i < TOPK; i++) {
            if (srow[i] == scol[i]) { dlist[nd++] = i; sphi += sw[i]; }
            else sxi += sw[i];
        }
        s_nd = nd; s_swphi = sphi; s_swxi = sxi;
    }
    if (tid < TOPK) swxi[tid] = (srow[tid] == scol[tid]) ? 0.f : sw[tid];
    __syncthreads();

    // xi layer-1: f32x2 packed 8x8 tile, W1 streamed in 32-row d-tiles
    int jA = lane * 4;
    float4 b1a = *(const float4*)(xi_b1 + jA);
    float4 b1c = *(const float4*)(xi_b1 + jA + 128);
    ull bp0 = pk2(b1a.x, b1a.y), bp1 = pk2(b1a.z, b1a.w);
    ull bp2 = pk2(b1c.x, b1c.y), bp3 = pk2(b1c.z, b1c.w);
    float hbar[8] = {0.f, 0.f, 0.f, 0.f, 0.f, 0.f, 0.f, 0.f};

    for (int iter = 0; iter < 2; iter++) {
        int i0 = wid * 8 + iter * 64;  // warp-uniform i tile
        ull accp[8][4];
        #pragma unroll
        for (int r = 0; r < 8; r++) {
            accp[r][0] = bp0; accp[r][1] = bp1; accp[r][2] = bp2; accp[r][3] = bp3;
        }
        for (int dt = 0; dt < 128 / DT; dt++) {
            for (int t = tid; t < DT * 256; t += 256)
                sW1t[t] = xi_w1[dt * DT * 256 + t];
            __syncthreads();
            #pragma unroll 4
            for (int dd = 0; dd < DT; dd++) {
                int d = dt * DT + dd;
                float4 x0 = *(const float4*)(sXpT + d * 128 + i0);
                float4 x1 = *(const float4*)(sXpT + d * 128 + i0 + 4);
                float4 wa = *(const float4*)(sW1t + dd * 256 + jA);
                float4 wc = *(const float4*)(sW1t + dd * 256 + jA + 128);
                ull wp0 = pk2(wa.x, wa.y), wp1 = pk2(wa.z, wa.w);
                ull wp2 = pk2(wc.x, wc.y), wp3 = pk2(wc.z, wc.w);
                float xv[8] = {x0.x, x0.y, x0.z, x0.w, x1.x, x1.y, x1.z, x1.w};
                #pragma unroll
                for (int r = 0; r < 8; r++) {
                    ull rr = pk2(xv[r], xv[r]);
                    fma2(accp[r][0], rr, wp0);
                    fma2(accp[r][1], rr, wp1);
                    fma2(accp[r][2], rr, wp2);
                    fma2(accp[r][3], rr, wp3);
                }
            }
            __syncthreads();
        }
        #pragma unroll
        for (int r = 0; r < 8; r++) {
            float wi = swxi[i0 + r];
            #pragma unroll
            for (int cp = 0; cp < 4; cp++) {
                float lo, hi;
                upk2(accp[r][cp], lo, hi);
                hbar[cp * 2]     += wi * fmaxf(lo, 0.f);
                hbar[cp * 2 + 1] += wi * fmaxf(hi, 0.f);
            }
        }
    }
    #pragma unroll
    for (int c = 0; c < 4; c++) {
        hpart[wid * 256 + jA + c]       = hbar[c];
        hpart[wid * 256 + jA + 128 + c] = hbar[4 + c];
    }
    __syncthreads();

    int j = tid;
    float hx = 0.f;
    #pragma unroll
    for (int g = 0; g < 8; g++) hx += hpart[g * 256 + j];
    hxs[j] = hx;

    // phi path (diagonal pairs only — typically 0-2 per batch)
    float hp = 0.f;
    int nd = s_nd;
    for (int t = 0; t < nd; t++) {
        int i = dlist[t];
        float acc = phi_b1[j];
        #pragma unroll 8
        for (int d = 0; d < DIM; d++) acc += sXpT[d * 128 + i] * phi_w1[d * HIDN + j];
        hp += sw[i] * fmaxf(acc, 0.f);
    }
    hps[j] = hp;
    __syncthreads();

    // layer-2 folded into pooling -> pooled[j], stored in hpart[0..255]
    {
        float out = s_swxi * xi_b2[j];
        #pragma unroll 8
        for (int k = 0; k < HIDN; k++) out += hxs[k] * xi_w2[k * HIDN + j];
        if (nd > 0) {
            out += s_swphi * phi_b2[j];
            #pragma unroll 8
            for (int k = 0; k < HIDN; k++) out += hps[k] * phi_w2[k * HIDN + j];
        }
        hpart[j] = out;             // pooled
    }
    __syncthreads();

    // rho layer-1: h[j] = relu(b1[j] + sum_k pooled[k]*w1[k][j]) -> hpart[256..511]
    {
        float acc = rho_b1[j];
        #pragma unroll 8
        for (int k = 0; k < HIDN; k++) acc += hpart[k] * rho_w1[k * HIDN + j];
        hpart[256 + j] = fmaxf(acc, 0.f);
    }
    __syncthreads();

    // rho layer-2: out[b][j] for j < 128
    if (tid < 128) {
        float o = rho_b2[tid];
        #pragma unroll 8
        for (int k = 0; k < HIDN; k++) o += hpart[256 + k] * rho_w2[k * 128 + tid];
        outp[b * 128 + tid] = o;
    }
}

// ---------------- launch ----------------
extern "C" void kernel_launch(void* const* d_in, const int* in_sizes, int n_in,
                              void* d_out, int out_size) {
    const float* x      = (const float*)d_in[0];
    const float* Wq     = (const float*)d_in[1];
    const float* bq     = (const float*)d_in[2];
    const float* Wk     = (const float*)d_in[3];
    const float* bk     = (const float*)d_in[4];
    const float* phi_w1 = (const float*)d_in[5];
    const float* phi_b1 = (const float*)d_in[6];
    const float* phi_w2 = (const float*)d_in[7];
    const float* phi_b2 = (const float*)d_in[8];
    const float* xi_w1  = (const float*)d_in[9];
    const float* xi_b1  = (const float*)d_in[10];
    const float* xi_w2  = (const float*)d_in[11];
    const float* xi_b2  = (const float*)d_in[12];
    const float* rho_w1 = (const float*)d_in[13];
    const float* rho_b1 = (const float*)d_in[14];
    const float* rho_w2 = (const float*)d_in[15];
    const float* rho_b2 = (const float*)d_in[16];
    float* out = (float*)d_out;

    int stSmem = ST_SMEM_FLOATS * sizeof(float);
    int prSmem = PR_SMEM_FLOATS * sizeof(float);
    cudaFuncSetAttribute(kScoresTopK, cudaFuncAttributeMaxDynamicSharedMemorySize, stSmem);
    cudaFuncSetAttribute(kPairs,      cudaFuncAttributeMaxDynamicSharedMemorySize, prSmem);

    kPrep<<<529, 256>>>(Wq, Wk, bq, bk);
    kScoresTopK<<<BATCH, 256, stSmem>>>(x);
    kPairs<<<BATCH, 256, prSmem>>>(x, xi_w1, xi_b1, xi_w2, xi_b2,
                                   phi_w1, phi_b1, phi_w2, phi_b2,
                                   rho_w1, rho_b1, rho_w2, rho_b2, out);
}